// round 13
// baseline (speedup 1.0000x reference)
#include <cuda_runtime.h>

// Round 13: stage-1 A operands direct from gmem (no staging, fewer barriers);
// stage-4 software-pipelined logits; weight staging overlapped with compute.

constexpr int NTHR = 256;
constexpr int NT = 200, NW = 100, CM = 256;

// u32 offsets
constexpr int XU   = 0;              // x/q/o [208][36]; S1: weight half0 [64][68]
constexpr int KU   = 7488;           // h_w/K ; S5: w_op half0
constexpr int VU   = 14976;          // h_t/V ; S5: w_op half1
constexpr int MISC = 22464;          // weight staging [128][36] / S1 half1 [64][68]
constexpr int SMEM_U = 27072;        // 108288 bytes

typedef unsigned u32t;

__device__ __forceinline__ unsigned packbf(float lo, float hi) {
    unsigned r;
    asm("cvt.rn.bf16x2.f32 %0, %1, %2;" : "=r"(r) : "f"(hi), "f"(lo));
    return r;
}
__device__ __forceinline__ void mma16816(float* d, const unsigned* a,
                                         unsigned b0, unsigned b1) {
    asm volatile(
        "mma.sync.aligned.m16n8k16.row.col.f32.bf16.bf16.f32 "
        "{%0,%1,%2,%3}, {%4,%5,%6,%7}, {%8,%9}, {%0,%1,%2,%3};"
        : "+f"(d[0]), "+f"(d[1]), "+f"(d[2]), "+f"(d[3])
        : "r"(a[0]), "r"(a[1]), "r"(a[2]), "r"(a[3]), "r"(b0), "r"(b1));
}
__device__ __forceinline__ void ldmT(unsigned& r0, unsigned& r1,
                                     unsigned& r2, unsigned& r3, unsigned addr) {
    asm volatile(
        "ldmatrix.sync.aligned.m8n8.x4.trans.shared.b16 {%0,%1,%2,%3}, [%4];"
        : "=r"(r0), "=r"(r1), "=r"(r2), "=r"(r3) : "r"(addr));
}
__device__ __forceinline__ float red2sum(float v) {
    v += __shfl_xor_sync(0xffffffffu, v, 1);
    v += __shfl_xor_sync(0xffffffffu, v, 2);
    return v;
}

__global__ __launch_bounds__(NTHR, 2) void wda_kernel(
    const float* __restrict__ turb, const float* __restrict__ weath,
    const float* __restrict__ w_t,  const float* __restrict__ b_t,
    const float* __restrict__ w_w,  const float* __restrict__ b_w,
    const float* __restrict__ g_t,  const float* __restrict__ be_t,
    const float* __restrict__ g_w,  const float* __restrict__ be_w,
    const float* __restrict__ w_qkv,const float* __restrict__ b_qkv,
    const float* __restrict__ w_ao, const float* __restrict__ b_ao,
    const float* __restrict__ w_op, const float* __restrict__ b_op,
    float* __restrict__ out)
{
    extern __shared__ u32t smu[];
    const int tid  = threadIdx.x;
    const int warp = tid >> 5, lane = tid & 31;
    const int g    = lane >> 2, tg = lane & 3;           // mma fragment coords
    const int lrow = lane & 15, lcol = (lane >> 4) * 4;  // ldmatrix coords
    unsigned sb;
    asm("{ .reg .u64 t; cvta.to.shared.u64 t, %1; cvt.u32.u64 %0, t; }"
        : "=r"(sb) : "l"(smu));
    const size_t s = blockIdx.x;
    const float* turb_s  = turb  + s * (size_t)(NT * CM);
    const float* weath_s = weath + s * (size_t)(NW * CM);
    float*       out_s   = out   + s * (size_t)(NT * CM);

    // zero pads: V rows 200..207 (stage-4 PV), h_w rows 100..111 (stage-2 PV)
    for (int i = tid; i < 8 * 36; i += NTHR)  smu[VU + 200 * 36 + i] = 0u;
    for (int i = tid; i < 12 * 36; i += NTHR) smu[KU + 100 * 36 + i] = 0u;

    // ===== Stage 1 (MMA): h = LN(x @ W^T + b); A direct from gmem =========
#pragma unroll 1
    for (int src = 0; src < 2; ++src) {
        const float* inp = src ? weath_s : turb_s;
        const float* Wg  = src ? w_w  : w_t;
        const float* bg  = src ? b_w  : b_t;
        const float* gg  = src ? g_w  : g_t;
        const float* beg = src ? be_w : be_t;
        const int rows   = src ? NW : NT;
        const int nT     = src ? 7 : 13;
        const int hb     = src ? KU : VU;

        __syncthreads();
        // stage full wT: k<128 -> XU[64][68], k>=128 -> MISC[64][68]
        for (int idx = tid; idx < 64 * 64; idx += NTHR) {
            const int d = idx >> 6, j = idx & 63;
            smu[XU + d * 68 + j] =
                packbf(Wg[d * 256 + 2 * j], Wg[d * 256 + 2 * j + 1]);
            smu[MISC + d * 68 + j] =
                packbf(Wg[d * 256 + 128 + 2 * j], Wg[d * 256 + 129 + 2 * j]);
        }
        __syncthreads();
#pragma unroll 1
        for (int tt = 0; tt < 2; ++tt) {
            const int ti = warp + tt * 8;
            if (ti >= nT) continue;
            const float* xr0 = inp + (size_t)min(ti * 16 + g, rows - 1) * CM;
            const float* xr1 = inp + (size_t)min(ti * 16 + 8 + g, rows - 1) * CM;
            float acc[32];
#pragma unroll
            for (int j = 0; j < 32; ++j) acc[j] = 0.f;
#pragma unroll 4
            for (int ks = 0; ks < 16; ++ks) {
                const int k0 = ks * 16 + 2 * tg;
                unsigned af[4];
                float2 v;
                v = *reinterpret_cast<const float2*>(xr0 + k0);
                af[0] = packbf(v.x, v.y);
                v = *reinterpret_cast<const float2*>(xr1 + k0);
                af[1] = packbf(v.x, v.y);
                v = *reinterpret_cast<const float2*>(xr0 + k0 + 8);
                af[2] = packbf(v.x, v.y);
                v = *reinterpret_cast<const float2*>(xr1 + k0 + 8);
                af[3] = packbf(v.x, v.y);
                const int base = (ks < 8) ? XU : MISC;
                const int co = (ks & 7) * 8 + tg;
#pragma unroll
                for (int nt = 0; nt < 8; ++nt) {
                    const int br = base + (nt * 8 + g) * 68 + co;
                    mma16816(&acc[nt * 4], af, smu[br], smu[br + 4]);
                }
            }
            // bias + LN + store
            float s0 = 0.f, q0 = 0.f, s1 = 0.f, q1 = 0.f;
#pragma unroll
            for (int nt = 0; nt < 8; ++nt) {
                const float2 bb = *reinterpret_cast<const float2*>(
                    bg + nt * 8 + 2 * tg);
                float* a = &acc[nt * 4];
                a[0] += bb.x; a[1] += bb.y; a[2] += bb.x; a[3] += bb.y;
                s0 += a[0] + a[1]; q0 += a[0]*a[0] + a[1]*a[1];
                s1 += a[2] + a[3]; q1 += a[2]*a[2] + a[3]*a[3];
            }
            s0 = red2sum(s0); q0 = red2sum(q0);
            s1 = red2sum(s1); q1 = red2sum(q1);
            const float mu0 = s0 * 0.015625f, mu1 = s1 * 0.015625f;
            const float rs0 = rsqrtf(q0 * 0.015625f - mu0 * mu0 + 1e-5f);
            const float rs1 = rsqrtf(q1 * 0.015625f - mu1 * mu1 + 1e-5f);
            const int r0 = ti * 16 + g, r1 = r0 + 8;
#pragma unroll
            for (int nt = 0; nt < 8; ++nt) {
                const float2 gm = *reinterpret_cast<const float2*>(
                    gg + nt * 8 + 2 * tg);
                const float2 be = *reinterpret_cast<const float2*>(
                    beg + nt * 8 + 2 * tg);
                const float* a = &acc[nt * 4];
                if (r0 < rows)
                    smu[hb + r0 * 36 + nt * 4 + tg] =
                        packbf((a[0]-mu0)*rs0*gm.x + be.x,
                               (a[1]-mu0)*rs0*gm.y + be.y);
                if (r1 < rows)
                    smu[hb + r1 * 36 + nt * 4 + tg] =
                        packbf((a[2]-mu1)*rs1*gm.x + be.x,
                               (a[3]-mu1)*rs1*gm.y + be.y);
            }
        }
    }
    __syncthreads();

    // stage qkv half0 weights (k,v rows 64..191) into MISC — overlaps stage 2
    for (int idx = tid; idx < 128 * 32; idx += NTHR) {
        const int d = idx >> 5, j = idx & 31;
        const float2 v = *reinterpret_cast<const float2*>(
            w_qkv + (64 + d) * 64 + 2 * j);
        smu[MISC + d * 36 + j] = packbf(v.x, v.y);
    }

    // ===== Stage 2 (MMA attention): x = softmax(h_t h_w^T / 8) h_w ========
#pragma unroll 1
    for (int tt = 0; tt < 2; ++tt) {
        const int ti = warp + tt * 8;
        if (ti < 13) {
            const int rbase = ti * 16;
            float d[13][4];
#pragma unroll
            for (int nt = 0; nt < 13; ++nt)
#pragma unroll
                for (int i = 0; i < 4; ++i) d[nt][i] = 0.f;
#pragma unroll
            for (int ks = 0; ks < 4; ++ks) {
                unsigned qa[4];
                const int ar = VU + (rbase + g) * 36 + ks * 8 + tg;
                qa[0] = smu[ar];     qa[1] = smu[ar + 288];
                qa[2] = smu[ar + 4]; qa[3] = smu[ar + 292];
#pragma unroll
                for (int nt = 0; nt < 13; ++nt) {
                    const int br = KU + (nt * 8 + g) * 36 + ks * 8 + tg;
                    mma16816(d[nt], qa, smu[br], smu[br + 4]);
                }
            }
            float s0 = 0.f, s1 = 0.f;
#pragma unroll
            for (int nt = 0; nt < 13; ++nt) {
                const int c0 = nt * 8 + 2 * tg;
                const bool ok0 = c0 < NW, ok1 = c0 + 1 < NW;
                d[nt][0] = ok0 ? __expf(d[nt][0] * 0.125f) : 0.f;
                d[nt][1] = ok1 ? __expf(d[nt][1] * 0.125f) : 0.f;
                d[nt][2] = ok0 ? __expf(d[nt][2] * 0.125f) : 0.f;
                d[nt][3] = ok1 ? __expf(d[nt][3] * 0.125f) : 0.f;
                s0 += d[nt][0] + d[nt][1];
                s1 += d[nt][2] + d[nt][3];
            }
            s0 = red2sum(s0); s1 = red2sum(s1);
            float o[8][4];
#pragma unroll
            for (int nt = 0; nt < 8; ++nt)
#pragma unroll
                for (int i = 0; i < 4; ++i) o[nt][i] = 0.f;
#pragma unroll
            for (int kt = 0; kt < 7; ++kt) {
                const float zz[4] = {0.f, 0.f, 0.f, 0.f};
                const float* dA = d[2 * kt];
                const float* dB = (2 * kt + 1 < 13) ? d[2 * kt + 1] : zz;
                unsigned a[4];
                a[0] = packbf(dA[0], dA[1]); a[1] = packbf(dA[2], dA[3]);
                a[2] = packbf(dB[0], dB[1]); a[3] = packbf(dB[2], dB[3]);
#pragma unroll
                for (int np = 0; np < 4; ++np) {
                    unsigned b0, b1, b2, b3;
                    const unsigned ad = sb + 4u *
                        (KU + (kt * 16 + lrow) * 36 + np * 8 + lcol);
                    ldmT(b0, b1, b2, b3, ad);
                    mma16816(o[2 * np],     a, b0, b1);
                    mma16816(o[2 * np + 1], a, b2, b3);
                }
            }
            const float i0 = 1.f / s0, i1 = 1.f / s1;
            const int r0 = rbase + g, r1 = r0 + 8;
#pragma unroll
            for (int nt = 0; nt < 8; ++nt) {
                if (r0 < NT)
                    smu[XU + r0 * 36 + nt * 4 + tg] =
                        packbf(o[nt][0] * i0, o[nt][1] * i0);
                if (r1 < NT)
                    smu[XU + r1 * 36 + nt * 4 + tg] =
                        packbf(o[nt][2] * i1, o[nt][3] * i1);
            }
        }
    }
    __syncthreads();

    // ===== Stage 3a (MMA): k,v = x @ W^T + b ===============================
#pragma unroll
    for (int tt = 0; tt < 2; ++tt) {
        const int ti = warp + tt * 8;
        if (ti < 13) {
            unsigned af[16];
#pragma unroll
            for (int ks = 0; ks < 4; ++ks) {
                const int ar = XU + (ti * 16 + g) * 36 + ks * 8 + tg;
                af[ks*4+0] = smu[ar];     af[ks*4+1] = smu[ar + 288];
                af[ks*4+2] = smu[ar + 4]; af[ks*4+3] = smu[ar + 292];
            }
            const int r0 = ti * 16 + g, r1 = r0 + 8;
            float acc[16][4];
#pragma unroll
            for (int nt = 0; nt < 16; ++nt)
#pragma unroll
                for (int i = 0; i < 4; ++i) acc[nt][i] = 0.f;
#pragma unroll
            for (int ks = 0; ks < 4; ++ks)
#pragma unroll
                for (int nt = 0; nt < 16; ++nt) {
                    const int br = MISC + (nt * 8 + g) * 36 + ks * 8 + tg;
                    mma16816(acc[nt], &af[ks * 4], smu[br], smu[br + 4]);
                }
#pragma unroll
            for (int nt = 0; nt < 16; ++nt) {
                const float2 bb = *reinterpret_cast<const float2*>(
                    b_qkv + 64 + nt * 8 + 2 * tg);
                const int base = (nt < 8) ? KU : VU;
                const int cc = (nt & 7) * 4 + tg;
                if (r0 < NT)
                    smu[base + r0 * 36 + cc] =
                        packbf(acc[nt][0] + bb.x, acc[nt][1] + bb.y);
                if (r1 < NT)
                    smu[base + r1 * 36 + cc] =
                        packbf(acc[nt][2] + bb.x, acc[nt][3] + bb.y);
            }
        }
    }
    __syncthreads();
    // stage q weights (rows 0..63)
    for (int idx = tid; idx < 64 * 32; idx += NTHR) {
        const int d = idx >> 5, j = idx & 31;
        const float2 v = *reinterpret_cast<const float2*>(w_qkv + d * 64 + 2 * j);
        smu[MISC + d * 36 + j] = packbf(v.x, v.y);
    }
    __syncthreads();

    // ===== Stage 3b (MMA): q = x @ Wq^T + b (overwrites x in XU) ==========
#pragma unroll
    for (int tt = 0; tt < 2; ++tt) {
        const int ti = warp + tt * 8;
        if (ti < 13) {
            unsigned af[16];
#pragma unroll
            for (int ks = 0; ks < 4; ++ks) {
                const int ar = XU + (ti * 16 + g) * 36 + ks * 8 + tg;
                af[ks*4+0] = smu[ar];     af[ks*4+1] = smu[ar + 288];
                af[ks*4+2] = smu[ar + 4]; af[ks*4+3] = smu[ar + 292];
            }
            const int r0 = ti * 16 + g, r1 = r0 + 8;
            float acc[8][4];
#pragma unroll
            for (int nt = 0; nt < 8; ++nt)
#pragma unroll
                for (int i = 0; i < 4; ++i) acc[nt][i] = 0.f;
#pragma unroll
            for (int ks = 0; ks < 4; ++ks)
#pragma unroll
                for (int nt = 0; nt < 8; ++nt) {
                    const int br = MISC + (nt * 8 + g) * 36 + ks * 8 + tg;
                    mma16816(acc[nt], &af[ks * 4], smu[br], smu[br + 4]);
                }
#pragma unroll
            for (int nt = 0; nt < 8; ++nt) {
                const float2 bb = *reinterpret_cast<const float2*>(
                    b_qkv + nt * 8 + 2 * tg);
                const int cc = nt * 4 + tg;
                if (r0 < NT)
                    smu[XU + r0 * 36 + cc] =
                        packbf(acc[nt][0] + bb.x, acc[nt][1] + bb.y);
                if (r1 < NT)
                    smu[XU + r1 * 36 + cc] =
                        packbf(acc[nt][2] + bb.x, acc[nt][3] + bb.y);
            }
        }
    }
    __syncthreads();

    // stage attn_out weights into MISC — overlaps stage 4
    for (int idx = tid; idx < 64 * 32; idx += NTHR) {
        const int d = idx >> 5, j = idx & 31;
        const float2 v = *reinterpret_cast<const float2*>(w_ao + d * 64 + 2 * j);
        smu[MISC + d * 36 + j] = packbf(v.x, v.y);
    }

    // ===== Stage 4 (MMA attention, pipelined): o = softmax(qk^T/4) v ======
#pragma unroll 1
    for (int u = warp; u < 52; u += 8) {
        const int ti = u >> 2, h = u & 3;
        const int rbase = ti * 16;
        unsigned qa[4];
        const int ar = XU + (rbase + g) * 36 + h * 8 + tg;
        qa[0] = smu[ar];     qa[1] = smu[ar + 288];
        qa[2] = smu[ar + 4]; qa[3] = smu[ar + 292];
        float dA[4] = {0.f,0.f,0.f,0.f}, dB[4] = {0.f,0.f,0.f,0.f};
        {
            const int br = KU + g * 36 + h * 8 + tg;
            mma16816(dA, qa, smu[br], smu[br + 4]);
            const int br2 = KU + (8 + g) * 36 + h * 8 + tg;
            mma16816(dB, qa, smu[br2], smu[br2 + 4]);
        }
        float s0 = 0.f, s1 = 0.f;
        float o0[4] = {0.f,0.f,0.f,0.f}, o1[4] = {0.f,0.f,0.f,0.f};
#pragma unroll
        for (int kt = 0; kt < 13; ++kt) {
            float nA[4] = {0.f,0.f,0.f,0.f}, nB[4] = {0.f,0.f,0.f,0.f};
            if (kt < 12) {          // prefetch next logits (overlaps exp/PV)
                const int br = KU + ((kt + 1) * 16 + g) * 36 + h * 8 + tg;
                mma16816(nA, qa, smu[br], smu[br + 4]);
                if (kt < 11) {
                    const int br2 = KU + ((kt + 1) * 16 + 8 + g) * 36 + h * 8 + tg;
                    mma16816(nB, qa, smu[br2], smu[br2 + 4]);
                }
            }
            const bool bv = kt < 12;
            const float eA0 = __expf(dA[0] * 0.25f);
            const float eA1 = __expf(dA[1] * 0.25f);
            const float eA2 = __expf(dA[2] * 0.25f);
            const float eA3 = __expf(dA[3] * 0.25f);
            const float eB0 = bv ? __expf(dB[0] * 0.25f) : 0.f;
            const float eB1 = bv ? __expf(dB[1] * 0.25f) : 0.f;
            const float eB2 = bv ? __expf(dB[2] * 0.25f) : 0.f;
            const float eB3 = bv ? __expf(dB[3] * 0.25f) : 0.f;
            s0 += eA0 + eA1 + eB0 + eB1;
            s1 += eA2 + eA3 + eB2 + eB3;
            unsigned a[4];
            a[0] = packbf(eA0, eA1); a[1] = packbf(eA2, eA3);
            a[2] = packbf(eB0, eB1); a[3] = packbf(eB2, eB3);
            unsigned b0, b1, b2, b3;
            const unsigned ad = sb + 4u *
                (VU + (kt * 16 + lrow) * 36 + h * 8 + lcol);
            ldmT(b0, b1, b2, b3, ad);
            mma16816(o0, a, b0, b1);
            mma16816(o1, a, b2, b3);
#pragma unroll
            for (int i = 0; i < 4; ++i) { dA[i] = nA[i]; dB[i] = nB[i]; }
        }
        s0 = red2sum(s0); s1 = red2sum(s1);
        const float i0 = 1.f / s0, i1 = 1.f / s1;
        const int r0 = rbase + g, r1 = r0 + 8;
        if (r0 < NT) {
            smu[XU + r0 * 36 + h * 8 + tg]     = packbf(o0[0] * i0, o0[1] * i0);
            smu[XU + r0 * 36 + h * 8 + 4 + tg] = packbf(o1[0] * i0, o1[1] * i0);
        }
        if (r1 < NT) {
            smu[XU + r1 * 36 + h * 8 + tg]     = packbf(o0[2] * i1, o0[3] * i1);
            smu[XU + r1 * 36 + h * 8 + 4 + tg] = packbf(o1[2] * i1, o1[3] * i1);
        }
    }
    __syncthreads();

    // stage out_proj weights into KU/VU (k/v dead)
    for (int idx = tid; idx < 128 * 32; idx += NTHR) {
        const int d = idx >> 5, j = idx & 31;
        const float2 v0 = *reinterpret_cast<const float2*>(w_op + d * 64 + 2 * j);
        smu[KU + d * 36 + j] = packbf(v0.x, v0.y);
        const float2 v1 = *reinterpret_cast<const float2*>(
            w_op + (128 + d) * 64 + 2 * j);
        smu[VU + d * 36 + j] = packbf(v1.x, v1.y);
    }
    __syncthreads();

    // ===== Stage 5 (MMA): A1 = o@aoT + b_ao; out = turb + A1@opT + b_op ===
#pragma unroll
    for (int tt = 0; tt < 2; ++tt) {
        const int ti = warp + tt * 8;
        if (ti < 13) {
            unsigned af[16];
#pragma unroll
            for (int ks = 0; ks < 4; ++ks) {
                const int ar = XU + (ti * 16 + g) * 36 + ks * 8 + tg;
                af[ks*4+0] = smu[ar];     af[ks*4+1] = smu[ar + 288];
                af[ks*4+2] = smu[ar + 4]; af[ks*4+3] = smu[ar + 292];
            }
            float acc1[8][4];
#pragma unroll
            for (int nt = 0; nt < 8; ++nt)
#pragma unroll
                for (int i = 0; i < 4; ++i) acc1[nt][i] = 0.f;
#pragma unroll
            for (int ks = 0; ks < 4; ++ks)
#pragma unroll
                for (int nt = 0; nt < 8; ++nt) {
                    const int br = MISC + (nt * 8 + g) * 36 + ks * 8 + tg;
                    mma16816(acc1[nt], &af[ks * 4], smu[br], smu[br + 4]);
                }
            unsigned a2[16];
#pragma unroll
            for (int t = 0; t < 4; ++t) {
                const float2 b0 = *reinterpret_cast<const float2*>(
                    b_ao + t * 16 + 2 * tg);
                const float2 b1 = *reinterpret_cast<const float2*>(
                    b_ao + t * 16 + 8 + 2 * tg);
                a2[t*4+0] = packbf(acc1[2*t][0] + b0.x,   acc1[2*t][1] + b0.y);
                a2[t*4+1] = packbf(acc1[2*t][2] + b0.x,   acc1[2*t][3] + b0.y);
                a2[t*4+2] = packbf(acc1[2*t+1][0] + b1.x, acc1[2*t+1][1] + b1.y);
                a2[t*4+3] = packbf(acc1[2*t+1][2] + b1.x, acc1[2*t+1][3] + b1.y);
            }
            const int r0 = ti * 16 + g, r1 = r0 + 8;
#pragma unroll 1
            for (int h2 = 0; h2 < 2; ++h2) {
                const int wb = h2 ? VU : KU;
                const int nb = h2 * 128;
                float acc2[16][4];
#pragma unroll
                for (int nt = 0; nt < 16; ++nt) {
                    const int c = nb + nt * 8 + 2 * tg;
                    const float2 bp = *reinterpret_cast<const float2*>(b_op + c);
                    float2 tA = make_float2(0.f, 0.f), tB = make_float2(0.f, 0.f);
                    if (r0 < NT) tA = *reinterpret_cast<const float2*>(
                        turb_s + (size_t)r0 * CM + c);
                    if (r1 < NT) tB = *reinterpret_cast<const float2*>(
                        turb_s + (size_t)r1 * CM + c);
                    acc2[nt][0] = bp.x + tA.x; acc2[nt][1] = bp.y + tA.y;
                    acc2[nt][2] = bp.x + tB.x; acc2[nt][3] = bp.y + tB.y;
                }
#pragma unroll
                for (int ks = 0; ks < 4; ++ks)
#pragma unroll
                    for (int nt = 0; nt < 16; ++nt) {
                        const int br = wb + (nt * 8 + g) * 36 + ks * 8 + tg;
                        mma16816(acc2[nt], &a2[ks * 4], smu[br], smu[br + 4]);
                    }
#pragma unroll
                for (int nt = 0; nt < 16; ++nt) {
                    const int c = nb + nt * 8 + 2 * tg;
                    if (r0 < NT)
                        *reinterpret_cast<float2*>(out_s + (size_t)r0 * CM + c) =
                            make_float2(acc2[nt][0], acc2[nt][1]);
                    if (r1 < NT)
                        *reinterpret_cast<float2*>(out_s + (size_t)r1 * CM + c) =
                            make_float2(acc2[nt][2], acc2[nt][3]);
                }
            }
        }
    }
}

extern "C" void kernel_launch(void* const* d_in, const int* in_sizes, int n_in,
                              void* d_out, int out_size)
{
    const float* turb  = (const float*)d_in[0];
    const float* weath = (const float*)d_in[1];
    const float* w_t   = (const float*)d_in[2];
    const float* b_t   = (const float*)d_in[3];
    const float* w_w   = (const float*)d_in[4];
    const float* b_w   = (const float*)d_in[5];
    const float* g_t   = (const float*)d_in[6];
    const float* be_t  = (const float*)d_in[7];
    const float* g_w   = (const float*)d_in[8];
    const float* be_w  = (const float*)d_in[9];
    const float* w_qkv = (const float*)d_in[10];
    const float* b_qkv = (const float*)d_in[11];
    const float* w_ao  = (const float*)d_in[12];
    const float* b_ao  = (const float*)d_in[13];
    const float* w_op  = (const float*)d_in[14];
    const float* b_op  = (const float*)d_in[15];
    float* out = (float*)d_out;

    const int S = in_sizes[0] / (NT * CM);   // 768
    const size_t smem = (size_t)SMEM_U * sizeof(unsigned);
    cudaFuncSetAttribute(wda_kernel, cudaFuncAttributeMaxDynamicSharedMemorySize,
                         (int)smem);
    wda_kernel<<<S, NTHR, smem>>>(turb, weath, w_t, b_t, w_w, b_w,
                                  g_t, be_t, g_w, be_w, w_qkv, b_qkv,
                                  w_ao, b_ao, w_op, b_op, out);
}

// round 14
// speedup vs baseline: 1.1684x; 1.1684x over previous
#include <cuda_runtime.h>

// Round 14: R12 stage-1 (smem-staged, coalesced) + R13's stage-4 pipeline and
// overlapped weight staging. 256 thr, 2 CTAs/SM.

constexpr int NTHR = 256;
constexpr int NT = 200, NW = 100, CM = 256;

constexpr int XU   = 0;              // x/q/o [208][36]; S1 A-staging
constexpr int KU   = 7488;           // h_w/K ; S5: w_op half0
constexpr int VU   = 14976;          // h_t/V ; S5: w_op half1
constexpr int MISC = 22464;          // [128][36] weight staging
constexpr int SMEM_U = 27072;        // 108288 bytes

typedef unsigned u32t;

__device__ __forceinline__ unsigned packbf(float lo, float hi) {
    unsigned r;
    asm("cvt.rn.bf16x2.f32 %0, %1, %2;" : "=r"(r) : "f"(hi), "f"(lo));
    return r;
}
__device__ __forceinline__ void mma16816(float* d, const unsigned* a,
                                         unsigned b0, unsigned b1) {
    asm volatile(
        "mma.sync.aligned.m16n8k16.row.col.f32.bf16.bf16.f32 "
        "{%0,%1,%2,%3}, {%4,%5,%6,%7}, {%8,%9}, {%0,%1,%2,%3};"
        : "+f"(d[0]), "+f"(d[1]), "+f"(d[2]), "+f"(d[3])
        : "r"(a[0]), "r"(a[1]), "r"(a[2]), "r"(a[3]), "r"(b0), "r"(b1));
}
__device__ __forceinline__ void ldmT(unsigned& r0, unsigned& r1,
                                     unsigned& r2, unsigned& r3, unsigned addr) {
    asm volatile(
        "ldmatrix.sync.aligned.m8n8.x4.trans.shared.b16 {%0,%1,%2,%3}, [%4];"
        : "=r"(r0), "=r"(r1), "=r"(r2), "=r"(r3) : "r"(addr));
}
__device__ __forceinline__ float red2sum(float v) {
    v += __shfl_xor_sync(0xffffffffu, v, 1);
    v += __shfl_xor_sync(0xffffffffu, v, 2);
    return v;
}

__global__ __launch_bounds__(NTHR, 2) void wda_kernel(
    const float* __restrict__ turb, const float* __restrict__ weath,
    const float* __restrict__ w_t,  const float* __restrict__ b_t,
    const float* __restrict__ w_w,  const float* __restrict__ b_w,
    const float* __restrict__ g_t,  const float* __restrict__ be_t,
    const float* __restrict__ g_w,  const float* __restrict__ be_w,
    const float* __restrict__ w_qkv,const float* __restrict__ b_qkv,
    const float* __restrict__ w_ao, const float* __restrict__ b_ao,
    const float* __restrict__ w_op, const float* __restrict__ b_op,
    float* __restrict__ out)
{
    extern __shared__ u32t smu[];
    const int tid  = threadIdx.x;
    const int warp = tid >> 5, lane = tid & 31;
    const int g    = lane >> 2, tg = lane & 3;
    const int lrow = lane & 15, lcol = (lane >> 4) * 4;
    unsigned sb;
    asm("{ .reg .u64 t; cvta.to.shared.u64 t, %1; cvt.u32.u64 %0, t; }"
        : "=r"(sb) : "l"(smu));
    const size_t s = blockIdx.x;
    const float* turb_s  = turb  + s * (size_t)(NT * CM);
    const float* weath_s = weath + s * (size_t)(NW * CM);
    float*       out_s   = out   + s * (size_t)(NT * CM);

    for (int i = tid; i < 8 * 36; i += NTHR)  smu[VU + 200 * 36 + i] = 0u;
    for (int i = tid; i < 12 * 36; i += NTHR) smu[KU + 100 * 36 + i] = 0u;

    // ===== Stage 1 (MMA): h = LN(x @ W^T + b) -> h_t in VU, h_w in KU =====
#pragma unroll 1
    for (int src = 0; src < 2; ++src) {
        const float* inp = src ? weath_s : turb_s;
        const float* Wg  = src ? w_w  : w_t;
        const float* bg  = src ? b_w  : b_t;
        const float* gg  = src ? g_w  : g_t;
        const float* beg = src ? be_w : be_t;
        const int rows   = src ? NW : NT;
        const int nT     = src ? 7 : 13;
        const int rstage = nT * 16;
        const int hb     = src ? KU : VU;
        float acc[2][32];
#pragma unroll
        for (int i = 0; i < 2; ++i)
#pragma unroll
            for (int j = 0; j < 32; ++j) acc[i][j] = 0.f;

#pragma unroll 1
        for (int kc = 0; kc < 4; ++kc) {
            __syncthreads();
            for (int idx = tid; idx < rstage * 32; idx += NTHR) {
                const int r = idx >> 5, j = idx & 31;
                const int rr = min(r, rows - 1);
                const float2 v = *reinterpret_cast<const float2*>(
                    inp + (size_t)rr * CM + kc * 64 + 2 * j);
                smu[XU + r * 36 + j] = packbf(v.x, v.y);
            }
            for (int idx = tid; idx < 64 * 32; idx += NTHR) {
                const int d = idx >> 5, j = idx & 31;
                const float2 v = *reinterpret_cast<const float2*>(
                    Wg + d * 256 + kc * 64 + 2 * j);
                smu[MISC + d * 36 + j] = packbf(v.x, v.y);
            }
            __syncthreads();
#pragma unroll
            for (int tt = 0; tt < 2; ++tt) {
                const int ti = warp + tt * 8;
                if (ti < nT) {
#pragma unroll
                    for (int ks = 0; ks < 4; ++ks) {
                        unsigned af[4];
                        const int ar = XU + (ti * 16 + g) * 36 + ks * 8 + tg;
                        af[0] = smu[ar];     af[1] = smu[ar + 288];
                        af[2] = smu[ar + 4]; af[3] = smu[ar + 292];
#pragma unroll
                        for (int nt = 0; nt < 8; ++nt) {
                            const int br = MISC + (nt * 8 + g) * 36 + ks * 8 + tg;
                            mma16816(&acc[tt][nt * 4], af, smu[br], smu[br + 4]);
                        }
                    }
                }
            }
        }
#pragma unroll
        for (int tt = 0; tt < 2; ++tt) {
            const int ti = warp + tt * 8;
            if (ti < nT) {
                float s0 = 0.f, q0 = 0.f, s1 = 0.f, q1 = 0.f;
#pragma unroll
                for (int nt = 0; nt < 8; ++nt) {
                    const float2 bb = *reinterpret_cast<const float2*>(
                        bg + nt * 8 + 2 * tg);
                    float* a = &acc[tt][nt * 4];
                    a[0] += bb.x; a[1] += bb.y; a[2] += bb.x; a[3] += bb.y;
                    s0 += a[0] + a[1]; q0 += a[0]*a[0] + a[1]*a[1];
                    s1 += a[2] + a[3]; q1 += a[2]*a[2] + a[3]*a[3];
                }
                s0 = red2sum(s0); q0 = red2sum(q0);
                s1 = red2sum(s1); q1 = red2sum(q1);
                const float mu0 = s0 * 0.015625f, mu1 = s1 * 0.015625f;
                const float rs0 = rsqrtf(q0 * 0.015625f - mu0 * mu0 + 1e-5f);
                const float rs1 = rsqrtf(q1 * 0.015625f - mu1 * mu1 + 1e-5f);
                const int r0 = ti * 16 + g, r1 = r0 + 8;
#pragma unroll
                for (int nt = 0; nt < 8; ++nt) {
                    const float2 gm = *reinterpret_cast<const float2*>(
                        gg + nt * 8 + 2 * tg);
                    const float2 be = *reinterpret_cast<const float2*>(
                        beg + nt * 8 + 2 * tg);
                    const float* a = &acc[tt][nt * 4];
                    if (r0 < rows)
                        smu[hb + r0 * 36 + nt * 4 + tg] =
                            packbf((a[0]-mu0)*rs0*gm.x + be.x,
                                   (a[1]-mu0)*rs0*gm.y + be.y);
                    if (r1 < rows)
                        smu[hb + r1 * 36 + nt * 4 + tg] =
                            packbf((a[2]-mu1)*rs1*gm.x + be.x,
                                   (a[3]-mu1)*rs1*gm.y + be.y);
                }
            }
        }
    }
    __syncthreads();

    // stage qkv k/v weights into MISC — overlaps stage 2 (MISC idle there)
    for (int idx = tid; idx < 128 * 32; idx += NTHR) {
        const int d = idx >> 5, j = idx & 31;
        const float2 v = *reinterpret_cast<const float2*>(
            w_qkv + (64 + d) * 64 + 2 * j);
        smu[MISC + d * 36 + j] = packbf(v.x, v.y);
    }

    // ===== Stage 2 (MMA attention): x = softmax(h_t h_w^T / 8) h_w ========
#pragma unroll 1
    for (int tt = 0; tt < 2; ++tt) {
        const int ti = warp + tt * 8;
        if (ti < 13) {
            const int rbase = ti * 16;
            float d[13][4];
#pragma unroll
            for (int nt = 0; nt < 13; ++nt)
#pragma unroll
                for (int i = 0; i < 4; ++i) d[nt][i] = 0.f;
#pragma unroll
            for (int ks = 0; ks < 4; ++ks) {
                unsigned qa[4];
                const int ar = VU + (rbase + g) * 36 + ks * 8 + tg;
                qa[0] = smu[ar];     qa[1] = smu[ar + 288];
                qa[2] = smu[ar + 4]; qa[3] = smu[ar + 292];
#pragma unroll
                for (int nt = 0; nt < 13; ++nt) {
                    const int br = KU + (nt * 8 + g) * 36 + ks * 8 + tg;
                    mma16816(d[nt], qa, smu[br], smu[br + 4]);
                }
            }
            float s0 = 0.f, s1 = 0.f;
#pragma unroll
            for (int nt = 0; nt < 13; ++nt) {
                const int c0 = nt * 8 + 2 * tg;
                const bool ok0 = c0 < NW, ok1 = c0 + 1 < NW;
                d[nt][0] = ok0 ? __expf(d[nt][0] * 0.125f) : 0.f;
                d[nt][1] = ok1 ? __expf(d[nt][1] * 0.125f) : 0.f;
                d[nt][2] = ok0 ? __expf(d[nt][2] * 0.125f) : 0.f;
                d[nt][3] = ok1 ? __expf(d[nt][3] * 0.125f) : 0.f;
                s0 += d[nt][0] + d[nt][1];
                s1 += d[nt][2] + d[nt][3];
            }
            s0 = red2sum(s0); s1 = red2sum(s1);
            float o[8][4];
#pragma unroll
            for (int nt = 0; nt < 8; ++nt)
#pragma unroll
                for (int i = 0; i < 4; ++i) o[nt][i] = 0.f;
#pragma unroll
            for (int kt = 0; kt < 7; ++kt) {
                const float zz[4] = {0.f, 0.f, 0.f, 0.f};
                const float* dA = d[2 * kt];
                const float* dB = (2 * kt + 1 < 13) ? d[2 * kt + 1] : zz;
                unsigned a[4];
                a[0] = packbf(dA[0], dA[1]); a[1] = packbf(dA[2], dA[3]);
                a[2] = packbf(dB[0], dB[1]); a[3] = packbf(dB[2], dB[3]);
#pragma unroll
                for (int np = 0; np < 4; ++np) {
                    unsigned b0, b1, b2, b3;
                    const unsigned ad = sb + 4u *
                        (KU + (kt * 16 + lrow) * 36 + np * 8 + lcol);
                    ldmT(b0, b1, b2, b3, ad);
                    mma16816(o[2 * np],     a, b0, b1);
                    mma16816(o[2 * np + 1], a, b2, b3);
                }
            }
            const float i0 = 1.f / s0, i1 = 1.f / s1;
            const int r0 = rbase + g, r1 = r0 + 8;
#pragma unroll
            for (int nt = 0; nt < 8; ++nt) {
                if (r0 < NT)
                    smu[XU + r0 * 36 + nt * 4 + tg] =
                        packbf(o[nt][0] * i0, o[nt][1] * i0);
                if (r1 < NT)
                    smu[XU + r1 * 36 + nt * 4 + tg] =
                        packbf(o[nt][2] * i1, o[nt][3] * i1);
            }
        }
    }
    __syncthreads();

    // ===== Stage 3a (MMA): k,v = x @ W^T + b ===============================
#pragma unroll
    for (int tt = 0; tt < 2; ++tt) {
        const int ti = warp + tt * 8;
        if (ti < 13) {
            unsigned af[16];
#pragma unroll
            for (int ks = 0; ks < 4; ++ks) {
                const int ar = XU + (ti * 16 + g) * 36 + ks * 8 + tg;
                af[ks*4+0] = smu[ar];     af[ks*4+1] = smu[ar + 288];
                af[ks*4+2] = smu[ar + 4]; af[ks*4+3] = smu[ar + 292];
            }
            const int r0 = ti * 16 + g, r1 = r0 + 8;
            float acc[16][4];
#pragma unroll
            for (int nt = 0; nt < 16; ++nt)
#pragma unroll
                for (int i = 0; i < 4; ++i) acc[nt][i] = 0.f;
#pragma unroll
            for (int ks = 0; ks < 4; ++ks)
#pragma unroll
                for (int nt = 0; nt < 16; ++nt) {
                    const int br = MISC + (nt * 8 + g) * 36 + ks * 8 + tg;
                    mma16816(acc[nt], &af[ks * 4], smu[br], smu[br + 4]);
                }
#pragma unroll
            for (int nt = 0; nt < 16; ++nt) {
                const float2 bb = *reinterpret_cast<const float2*>(
                    b_qkv + 64 + nt * 8 + 2 * tg);
                const int base = (nt < 8) ? KU : VU;
                const int cc = (nt & 7) * 4 + tg;
                if (r0 < NT)
                    smu[base + r0 * 36 + cc] =
                        packbf(acc[nt][0] + bb.x, acc[nt][1] + bb.y);
                if (r1 < NT)
                    smu[base + r1 * 36 + cc] =
                        packbf(acc[nt][2] + bb.x, acc[nt][3] + bb.y);
            }
        }
    }
    __syncthreads();
    for (int idx = tid; idx < 64 * 32; idx += NTHR) {
        const int d = idx >> 5, j = idx & 31;
        const float2 v = *reinterpret_cast<const float2*>(w_qkv + d * 64 + 2 * j);
        smu[MISC + d * 36 + j] = packbf(v.x, v.y);
    }
    __syncthreads();

    // ===== Stage 3b (MMA): q = x @ Wq^T + b (overwrites x in XU) ==========
#pragma unroll
    for (int tt = 0; tt < 2; ++tt) {
        const int ti = warp + tt * 8;
        if (ti < 13) {
            unsigned af[16];
#pragma unroll
            for (int ks = 0; ks < 4; ++ks) {
                const int ar = XU + (ti * 16 + g) * 36 + ks * 8 + tg;
                af[ks*4+0] = smu[ar];     af[ks*4+1] = smu[ar + 288];
                af[ks*4+2] = smu[ar + 4]; af[ks*4+3] = smu[ar + 292];
            }
            const int r0 = ti * 16 + g, r1 = r0 + 8;
            float acc[8][4];
#pragma unroll
            for (int nt = 0; nt < 8; ++nt)
#pragma unroll
                for (int i = 0; i < 4; ++i) acc[nt][i] = 0.f;
#pragma unroll
            for (int ks = 0; ks < 4; ++ks)
#pragma unroll
                for (int nt = 0; nt < 8; ++nt) {
                    const int br = MISC + (nt * 8 + g) * 36 + ks * 8 + tg;
                    mma16816(acc[nt], &af[ks * 4], smu[br], smu[br + 4]);
                }
#pragma unroll
            for (int nt = 0; nt < 8; ++nt) {
                const float2 bb = *reinterpret_cast<const float2*>(
                    b_qkv + nt * 8 + 2 * tg);
                const int cc = nt * 4 + tg;
                if (r0 < NT)
                    smu[XU + r0 * 36 + cc] =
                        packbf(acc[nt][0] + bb.x, acc[nt][1] + bb.y);
                if (r1 < NT)
                    smu[XU + r1 * 36 + cc] =
                        packbf(acc[nt][2] + bb.x, acc[nt][3] + bb.y);
            }
        }
    }
    __syncthreads();

    // stage attn_out weights — overlaps stage 4 (MISC idle there)
    for (int idx = tid; idx < 64 * 32; idx += NTHR) {
        const int d = idx >> 5, j = idx & 31;
        const float2 v = *reinterpret_cast<const float2*>(w_ao + d * 64 + 2 * j);
        smu[MISC + d * 36 + j] = packbf(v.x, v.y);
    }

    // ===== Stage 4 (MMA attention, pipelined): o = softmax(qk^T/4) v ======
#pragma unroll 1
    for (int u = warp; u < 52; u += 8) {
        const int ti = u >> 2, h = u & 3;
        const int rbase = ti * 16;
        unsigned qa[4];
        const int ar = XU + (rbase + g) * 36 + h * 8 + tg;
        qa[0] = smu[ar];     qa[1] = smu[ar + 288];
        qa[2] = smu[ar + 4]; qa[3] = smu[ar + 292];
        float dA[4] = {0.f,0.f,0.f,0.f}, dB[4] = {0.f,0.f,0.f,0.f};
        {
            const int br = KU + g * 36 + h * 8 + tg;
            mma16816(dA, qa, smu[br], smu[br + 4]);
            const int br2 = KU + (8 + g) * 36 + h * 8 + tg;
            mma16816(dB, qa, smu[br2], smu[br2 + 4]);
        }
        float s0 = 0.f, s1 = 0.f;
        float o0[4] = {0.f,0.f,0.f,0.f}, o1[4] = {0.f,0.f,0.f,0.f};
#pragma unroll
        for (int kt = 0; kt < 13; ++kt) {
            float nA[4] = {0.f,0.f,0.f,0.f}, nB[4] = {0.f,0.f,0.f,0.f};
            if (kt < 12) {
                const int br = KU + ((kt + 1) * 16 + g) * 36 + h * 8 + tg;
                mma16816(nA, qa, smu[br], smu[br + 4]);
                if (kt < 11) {
                    const int br2 = KU + ((kt + 1) * 16 + 8 + g) * 36 + h * 8 + tg;
                    mma16816(nB, qa, smu[br2], smu[br2 + 4]);
                }
            }
            const bool bv = kt < 12;
            const float eA0 = __expf(dA[0] * 0.25f);
            const float eA1 = __expf(dA[1] * 0.25f);
            const float eA2 = __expf(dA[2] * 0.25f);
            const float eA3 = __expf(dA[3] * 0.25f);
            const float eB0 = bv ? __expf(dB[0] * 0.25f) : 0.f;
            const float eB1 = bv ? __expf(dB[1] * 0.25f) : 0.f;
            const float eB2 = bv ? __expf(dB[2] * 0.25f) : 0.f;
            const float eB3 = bv ? __expf(dB[3] * 0.25f) : 0.f;
            s0 += eA0 + eA1 + eB0 + eB1;
            s1 += eA2 + eA3 + eB2 + eB3;
            unsigned a[4];
            a[0] = packbf(eA0, eA1); a[1] = packbf(eA2, eA3);
            a[2] = packbf(eB0, eB1); a[3] = packbf(eB2, eB3);
            unsigned b0, b1, b2, b3;
            const unsigned ad = sb + 4u *
                (VU + (kt * 16 + lrow) * 36 + h * 8 + lcol);
            ldmT(b0, b1, b2, b3, ad);
            mma16816(o0, a, b0, b1);
            mma16816(o1, a, b2, b3);
#pragma unroll
            for (int i = 0; i < 4; ++i) { dA[i] = nA[i]; dB[i] = nB[i]; }
        }
        s0 = red2sum(s0); s1 = red2sum(s1);
        const float i0 = 1.f / s0, i1 = 1.f / s1;
        const int r0 = rbase + g, r1 = r0 + 8;
        if (r0 < NT) {
            smu[XU + r0 * 36 + h * 8 + tg]     = packbf(o0[0] * i0, o0[1] * i0);
            smu[XU + r0 * 36 + h * 8 + 4 + tg] = packbf(o1[0] * i0, o1[1] * i0);
        }
        if (r1 < NT) {
            smu[XU + r1 * 36 + h * 8 + tg]     = packbf(o0[2] * i1, o0[3] * i1);
            smu[XU + r1 * 36 + h * 8 + 4 + tg] = packbf(o1[2] * i1, o1[3] * i1);
        }
    }
    __syncthreads();

    // stage out_proj weights into KU/VU (k/v dead)
    for (int idx = tid; idx < 128 * 32; idx += NTHR) {
        const int d = idx >> 5, j = idx & 31;
        const float2 v0 = *reinterpret_cast<const float2*>(w_op + d * 64 + 2 * j);
        smu[KU + d * 36 + j] = packbf(v0.x, v0.y);
        const float2 v1 = *reinterpret_cast<const float2*>(
            w_op + (128 + d) * 64 + 2 * j);
        smu[VU + d * 36 + j] = packbf(v1.x, v1.y);
    }
    __syncthreads();

    // ===== Stage 5 (MMA): A1 = o@aoT + b_ao; out = turb + A1@opT + b_op ===
#pragma unroll
    for (int tt = 0; tt < 2; ++tt) {
        const int ti = warp + tt * 8;
        if (ti < 13) {
            unsigned af[16];
#pragma unroll
            for (int ks = 0; ks < 4; ++ks) {
                const int ar = XU + (ti * 16 + g) * 36 + ks * 8 + tg;
                af[ks*4+0] = smu[ar];     af[ks*4+1] = smu[ar + 288];
                af[ks*4+2] = smu[ar + 4]; af[ks*4+3] = smu[ar + 292];
            }
            float acc1[8][4];
#pragma unroll
            for (int nt = 0; nt < 8; ++nt)
#pragma unroll
                for (int i = 0; i < 4; ++i) acc1[nt][i] = 0.f;
#pragma unroll
            for (int ks = 0; ks < 4; ++ks)
#pragma unroll
                for (int nt = 0; nt < 8; ++nt) {
                    const int br = MISC + (nt * 8 + g) * 36 + ks * 8 + tg;
                    mma16816(acc1[nt], &af[ks * 4], smu[br], smu[br + 4]);
                }
            unsigned a2[16];
#pragma unroll
            for (int t = 0; t < 4; ++t) {
                const float2 b0 = *reinterpret_cast<const float2*>(
                    b_ao + t * 16 + 2 * tg);
                const float2 b1 = *reinterpret_cast<const float2*>(
                    b_ao + t * 16 + 8 + 2 * tg);
                a2[t*4+0] = packbf(acc1[2*t][0] + b0.x,   acc1[2*t][1] + b0.y);
                a2[t*4+1] = packbf(acc1[2*t][2] + b0.x,   acc1[2*t][3] + b0.y);
                a2[t*4+2] = packbf(acc1[2*t+1][0] + b1.x, acc1[2*t+1][1] + b1.y);
                a2[t*4+3] = packbf(acc1[2*t+1][2] + b1.x, acc1[2*t+1][3] + b1.y);
            }
            const int r0 = ti * 16 + g, r1 = r0 + 8;
#pragma unroll 1
            for (int h2 = 0; h2 < 2; ++h2) {
                const int wb = h2 ? VU : KU;
                const int nb = h2 * 128;
                float acc2[16][4];
#pragma unroll
                for (int nt = 0; nt < 16; ++nt) {
                    const int c = nb + nt * 8 + 2 * tg;
                    const float2 bp = *reinterpret_cast<const float2*>(b_op + c);
                    float2 tA = make_float2(0.f, 0.f), tB = make_float2(0.f, 0.f);
                    if (r0 < NT) tA = *reinterpret_cast<const float2*>(
                        turb_s + (size_t)r0 * CM + c);
                    if (r1 < NT) tB = *reinterpret_cast<const float2*>(
                        turb_s + (size_t)r1 * CM + c);
                    acc2[nt][0] = bp.x + tA.x; acc2[nt][1] = bp.y + tA.y;
                    acc2[nt][2] = bp.x + tB.x; acc2[nt][3] = bp.y + tB.y;
                }
#pragma unroll
                for (int ks = 0; ks < 4; ++ks)
#pragma unroll
                    for (int nt = 0; nt < 16; ++nt) {
                        const int br = wb + (nt * 8 + g) * 36 + ks * 8 + tg;
                        mma16816(acc2[nt], &a2[ks * 4], smu[br], smu[br + 4]);
                    }
#pragma unroll
                for (int nt = 0; nt < 16; ++nt) {
                    const int c = nb + nt * 8 + 2 * tg;
                    if (r0 < NT)
                        *reinterpret_cast<float2*>(out_s + (size_t)r0 * CM + c) =
                            make_float2(acc2[nt][0], acc2[nt][1]);
                    if (r1 < NT)
                        *reinterpret_cast<float2*>(out_s + (size_t)r1 * CM + c) =
                            make_float2(acc2[nt][2], acc2[nt][3]);
                }
            }
        }
    }
}

extern "C" void kernel_launch(void* const* d_in, const int* in_sizes, int n_in,
                              void* d_out, int out_size)
{
    const float* turb  = (const float*)d_in[0];
    const float* weath = (const float*)d_in[1];
    const float* w_t   = (const float*)d_in[2];
    const float* b_t   = (const float*)d_in[3];
    const float* w_w   = (const float*)d_in[4];
    const float* b_w   = (const float*)d_in[5];
    const float* g_t   = (const float*)d_in[6];
    const float* be_t  = (const float*)d_in[7];
    const float* g_w   = (const float*)d_in[8];
    const float* be_w  = (const float*)d_in[9];
    const float* w_qkv = (const float*)d_in[10];
    const float* b_qkv = (const float*)d_in[11];
    const float* w_ao  = (const float*)d_in[12];
    const float* b_ao  = (const float*)d_in[13];
    const float* w_op  = (const float*)d_in[14];
    const float* b_op  = (const float*)d_in[15];
    float* out = (float*)d_out;

    const int S = in_sizes[0] / (NT * CM);   // 768
    const size_t smem = (size_t)SMEM_U * sizeof(unsigned);
    cudaFuncSetAttribute(wda_kernel, cudaFuncAttributeMaxDynamicSharedMemorySize,
                         (int)smem);
    wda_kernel<<<S, NTHR, smem>>>(turb, weath, w_t, b_t, w_w, b_w,
                                  g_t, be_t, g_w, be_w, w_qkv, b_qkv,
                                  w_ao, b_ao, w_op, b_op, out);
}